// round 3
// baseline (speedup 1.0000x reference)
#include <cuda_runtime.h>
#include <cstdint>

// Problem constants (fixed by the dataset)
#define BATCH   4
#define DDIM    256
#define NPTS    4096
#define MSTRIDE 4097          // mat_assign_sublines row stride (n+1)
#define MARGIN_F 0.5f
#define MAXDIST_F 10000.0f
#define BIG_F 1000000000.0f

// Scratch: materialized "neg" matrix (dist where ov<=0 else MAX_DIST), 256 MiB
__device__ float g_neg[(size_t)BATCH * NPTS * NPTS];
__device__ float g_pos0[BATCH][NPTS];
__device__ float g_pos1[BATCH][NPTS];
__device__ float g_mn0[BATCH][NPTS];
__device__ float g_mn1[BATCH][NPTS];

// ---------------------------------------------------------------------------
// init: pos = 0, mn = BIG  (graph-replay safe: re-initialized every launch)
// ---------------------------------------------------------------------------
__global__ void init_kernel() {
    int idx = blockIdx.x * blockDim.x + threadIdx.x;
    if (idx < BATCH * NPTS) {
        ((float*)g_pos0)[idx] = 0.0f;
        ((float*)g_pos1)[idx] = 0.0f;
        ((float*)g_mn0)[idx]  = BIG_F;
        ((float*)g_mn1)[idx]  = BIG_F;
    }
}

// ---------------------------------------------------------------------------
// pass1: fused SGEMM (f32x2 packed FMA) + match-mask row/col max + neg store
//   C[i,j] = sum_k desc0[b,k,i] * desc1[b,k,j]   (both K-major, n contiguous)
//   tile 128x128, BK=16, 256 threads, 8x8 per thread
// ---------------------------------------------------------------------------
__global__ __launch_bounds__(256, 2)
void pass1_kernel(const float* __restrict__ d0,
                  const float* __restrict__ d1,
                  const float* __restrict__ mat) {
    const int b  = blockIdx.z;
    const int i0 = blockIdx.y * 128;
    const int j0 = blockIdx.x * 128;

    const float* A = d0 + (size_t)b * DDIM * NPTS;
    const float* Bm = d1 + (size_t)b * DDIM * NPTS;

    __shared__ __align__(16) float As[16][128];
    __shared__ __align__(16) float Bs[16][128];

    const int tid = threadIdx.x;
    const int tx = tid & 15;       // 0..15 -> col group (8 cols)
    const int ty = tid >> 4;       // 0..15 -> row group (8 rows)

    // packed f32x2 accumulators: acc[r][cpair]
    unsigned long long acc[8][4];
#pragma unroll
    for (int r = 0; r < 8; r++)
#pragma unroll
        for (int c = 0; c < 4; c++) acc[r][c] = 0ULL;

    const int lr = tid >> 4;          // load row 0..15
    const int lc = (tid & 15) * 8;    // load col (8 floats)

    for (int k0 = 0; k0 < DDIM; k0 += 16) {
        __syncthreads();
        const float4* ag = (const float4*)(A  + (size_t)(k0 + lr) * NPTS + i0 + lc);
        const float4* bg = (const float4*)(Bm + (size_t)(k0 + lr) * NPTS + j0 + lc);
        *(float4*)&As[lr][lc]     = ag[0];
        *(float4*)&As[lr][lc + 4] = ag[1];
        *(float4*)&Bs[lr][lc]     = bg[0];
        *(float4*)&Bs[lr][lc + 4] = bg[1];
        __syncthreads();

#pragma unroll
        for (int kk = 0; kk < 16; kk++) {
            unsigned long long bp[4];
#pragma unroll
            for (int c = 0; c < 4; c++)
                bp[c] = *(const unsigned long long*)&Bs[kk][tx * 8 + c * 2];
#pragma unroll
            for (int r = 0; r < 8; r++) {
                float a = As[kk][ty * 8 + r];
                unsigned long long ad;
                asm("mov.b64 %0, {%1, %1};" : "=l"(ad) : "f"(a));
#pragma unroll
                for (int c = 0; c < 4; c++)
                    asm("fma.rn.f32x2 %0, %1, %2, %0;"
                        : "+l"(acc[r][c]) : "l"(ad), "l"(bp[c]));
            }
        }
    }

    // ---- epilogue: dist, masks, neg store, row/col max ----
    float rmax[8], cmax[8];
#pragma unroll
    for (int r = 0; r < 8; r++) { rmax[r] = 0.0f; cmax[r] = 0.0f; }

    const float* Mbase  = mat + (size_t)b * MSTRIDE * MSTRIDE;
    float* negbase = g_neg + (size_t)b * NPTS * NPTS;

#pragma unroll
    for (int r = 0; r < 8; r++) {
        const int i = i0 + ty * 8 + r;
        const float* Mr = Mbase + (size_t)i * MSTRIDE + j0 + tx * 8;
        float* Nr = negbase + (size_t)i * NPTS + j0 + tx * 8;

        float fc[8];
#pragma unroll
        for (int c = 0; c < 4; c++)
            asm("mov.b64 {%0, %1}, %2;"
                : "=f"(fc[2 * c]), "=f"(fc[2 * c + 1]) : "l"(acc[r][c]));

        float nv[8];
#pragma unroll
        for (int c = 0; c < 8; c++) {
            float dist = fmaf(-2.0f, fc[c], 2.0f);
            float ov = __ldg(Mr + c);
            if (ov > 0.3f) {
                rmax[r] = fmaxf(rmax[r], dist);
                cmax[c] = fmaxf(cmax[c], dist);
            }
            nv[c] = (ov <= 0.0f) ? dist : MAXDIST_F;
        }
        *(float4*)Nr       = make_float4(nv[0], nv[1], nv[2], nv[3]);
        *(float4*)(Nr + 4) = make_float4(nv[4], nv[5], nv[6], nv[7]);
    }

    // row max: reduce over the 16 tx lanes (16-aligned groups within warp)
#pragma unroll
    for (int r = 0; r < 8; r++) {
#pragma unroll
        for (int s = 8; s > 0; s >>= 1)
            rmax[r] = fmaxf(rmax[r], __shfl_xor_sync(0xffffffffu, rmax[r], s));
    }
    if (tx == 0) {
#pragma unroll
        for (int r = 0; r < 8; r++)
            atomicMax((int*)&g_pos0[b][i0 + ty * 8 + r], __float_as_int(rmax[r]));
    }

    // col max: via smem (reuse As region, 16x128 floats)
    __syncthreads();
    float* cbuf = (float*)As;
#pragma unroll
    for (int c = 0; c < 8; c++)
        cbuf[ty * 128 + tx * 8 + c] = cmax[c];
    __syncthreads();
    if (tid < 128) {
        float m = 0.0f;
#pragma unroll
        for (int rr = 0; rr < 16; rr++)
            m = fmaxf(m, cbuf[rr * 128 + tid]);
        atomicMax((int*)&g_pos1[b][j0 + tid], __float_as_int(m));
    }
}

// ---------------------------------------------------------------------------
// pass2: masked min using finalized pos0/pos1 against stored neg
// ---------------------------------------------------------------------------
__global__ __launch_bounds__(256)
void pass2_kernel() {
    const int b  = blockIdx.z;
    const int i0 = blockIdx.y * 128;
    const int j0 = blockIdx.x * 128;

    const int tid = threadIdx.x;
    const int tx = tid & 15;
    const int ty = tid >> 4;

    __shared__ float cbuf[16 * 128];

    const float* negbase = g_neg + (size_t)b * NPTS * NPTS;

    float p1[8];
#pragma unroll
    for (int c = 0; c < 8; c++) p1[c] = g_pos1[b][j0 + tx * 8 + c];

    float rmin[8], cmin[8];
#pragma unroll
    for (int r = 0; r < 8; r++) { rmin[r] = BIG_F; cmin[r] = BIG_F; }

#pragma unroll
    for (int r = 0; r < 8; r++) {
        const int i = i0 + ty * 8 + r;
        const float p0 = g_pos0[b][i];
        const float p0hi = p0 + MARGIN_F;
        const float* Nr = negbase + (size_t)i * NPTS + j0 + tx * 8;
        float4 v0 = *(const float4*)Nr;
        float4 v1 = *(const float4*)(Nr + 4);
        float nv[8] = {v0.x, v0.y, v0.z, v0.w, v1.x, v1.y, v1.z, v1.w};
#pragma unroll
        for (int c = 0; c < 8; c++) {
            float v = nv[c];
            if (v > p0 && v < p0hi)           rmin[r] = fminf(rmin[r], v);
            if (v > p1[c] && v < p1[c] + MARGIN_F) cmin[c] = fminf(cmin[c], v);
        }
    }

    // row min reduce over tx lanes
#pragma unroll
    for (int r = 0; r < 8; r++) {
#pragma unroll
        for (int s = 8; s > 0; s >>= 1)
            rmin[r] = fminf(rmin[r], __shfl_xor_sync(0xffffffffu, rmin[r], s));
    }
    if (tx == 0) {
#pragma unroll
        for (int r = 0; r < 8; r++)
            atomicMin((int*)&g_mn0[b][i0 + ty * 8 + r], __float_as_int(rmin[r]));
    }

    // col min reduce via smem
#pragma unroll
    for (int c = 0; c < 8; c++)
        cbuf[ty * 128 + tx * 8 + c] = cmin[c];
    __syncthreads();
    if (tid < 128) {
        float m = BIG_F;
#pragma unroll
        for (int rr = 0; rr < 16; rr++)
            m = fminf(m, cbuf[rr * 128 + tid]);
        atomicMin((int*)&g_mn1[b][j0 + tid], __float_as_int(m));
    }
}

// ---------------------------------------------------------------------------
// final: single-block reduction over 2*b*n = 32768 entries -> 3 outputs
// ---------------------------------------------------------------------------
__global__ void final_kernel(float* __restrict__ out) {
    const int tid = threadIdx.x;   // 1024 threads
    float sum = 0.0f, cnt = 0.0f, hp = -BIG_F, hn = BIG_F;

    for (int idx = tid; idx < 2 * BATCH * NPTS; idx += 1024) {
        int b = idx >> 13;           // 8192 per batch
        int r = idx & 8191;
        float pos, mn;
        if (r < NPTS) { pos = g_pos0[b][r]; mn = g_mn0[b][r]; }
        else          { pos = g_pos1[b][r - NPTS]; mn = g_mn1[b][r - NPTS]; }
        bool has = (mn < BIG_F);
        bool valid = (pos > 0.0f) && has;
        if (valid) {
            sum += fmaxf(pos - mn + 1.0f, 0.0f);
            cnt += 1.0f;
            hp = fmaxf(hp, pos);
            hn = fminf(hn, mn);
        }
    }

    __shared__ float s_sum[32], s_cnt[32], s_hp[32], s_hn[32];
#pragma unroll
    for (int s = 16; s > 0; s >>= 1) {
        sum += __shfl_xor_sync(0xffffffffu, sum, s);
        cnt += __shfl_xor_sync(0xffffffffu, cnt, s);
        hp = fmaxf(hp, __shfl_xor_sync(0xffffffffu, hp, s));
        hn = fminf(hn, __shfl_xor_sync(0xffffffffu, hn, s));
    }
    if ((tid & 31) == 0) {
        s_sum[tid >> 5] = sum; s_cnt[tid >> 5] = cnt;
        s_hp[tid >> 5] = hp;   s_hn[tid >> 5] = hn;
    }
    __syncthreads();
    if (tid < 32) {
        sum = s_sum[tid]; cnt = s_cnt[tid]; hp = s_hp[tid]; hn = s_hn[tid];
#pragma unroll
        for (int s = 16; s > 0; s >>= 1) {
            sum += __shfl_xor_sync(0xffffffffu, sum, s);
            cnt += __shfl_xor_sync(0xffffffffu, cnt, s);
            hp = fmaxf(hp, __shfl_xor_sync(0xffffffffu, hp, s));
            hn = fminf(hn, __shfl_xor_sync(0xffffffffu, hn, s));
        }
        if (tid == 0) {
            out[0] = sum / fmaxf(cnt, 1.0f);
            out[1] = hp;
            out[2] = hn;
        }
    }
}

// ---------------------------------------------------------------------------
extern "C" void kernel_launch(void* const* d_in, const int* in_sizes, int n_in,
                              void* d_out, int out_size) {
    const float* desc0 = (const float*)d_in[0];
    const float* desc1 = (const float*)d_in[1];
    const float* mat   = (const float*)d_in[2];
    float* out = (float*)d_out;

    init_kernel<<<16, 1024>>>();
    dim3 grid(NPTS / 128, NPTS / 128, BATCH);
    pass1_kernel<<<grid, 256>>>(desc0, desc1, mat);
    pass2_kernel<<<grid, 256>>>();
    final_kernel<<<1, 1024>>>(out);
}

// round 4
// speedup vs baseline: 1.9474x; 1.9474x over previous
#include <cuda_runtime.h>
#include <cuda_bf16.h>
#include <cstdint>

#define BATCH   4
#define DDIM    256
#define NPTS    4096
#define MSTRIDE 4097
#define MARGIN_F 0.5f
#define MAXDIST_F 10000.0f
#define BIG_F 1000000000.0f

// ---------------- scratch ----------------
__device__ float g_neg[(size_t)BATCH * NPTS * NPTS];          // 256 MiB
__device__ float g_pos0[BATCH][NPTS];
__device__ float g_pos1[BATCH][NPTS];
__device__ float g_mn0[BATCH][NPTS];
__device__ float g_mn1[BATCH][NPTS];
// split-bf16 inputs: x = hi + lo
__device__ __nv_bfloat16 g_hi0[(size_t)BATCH * DDIM * NPTS];
__device__ __nv_bfloat16 g_lo0[(size_t)BATCH * DDIM * NPTS];
__device__ __nv_bfloat16 g_hi1[(size_t)BATCH * DDIM * NPTS];
__device__ __nv_bfloat16 g_lo1[(size_t)BATCH * DDIM * NPTS];
// final reduction partials
__device__ float g_psum[64], g_pcnt[64], g_php[64], g_phn[64];

// ---------------- ptx helpers ----------------
#define LDSM_T4(r0,r1,r2,r3, addr)                                              \
    asm volatile("ldmatrix.sync.aligned.m8n8.x4.trans.shared.b16 "              \
                 "{%0,%1,%2,%3}, [%4];"                                         \
                 : "=r"(r0), "=r"(r1), "=r"(r2), "=r"(r3) : "r"(addr))

#define MMA16816(d, a, b0, b1)                                                  \
    asm volatile("mma.sync.aligned.m16n8k16.row.col.f32.bf16.bf16.f32 "         \
                 "{%0,%1,%2,%3},{%4,%5,%6,%7},{%8,%9},{%0,%1,%2,%3};"           \
                 : "+f"(d[0]), "+f"(d[1]), "+f"(d[2]), "+f"(d[3])               \
                 : "r"(a[0]), "r"(a[1]), "r"(a[2]), "r"(a[3]),                  \
                   "r"(b0), "r"(b1))

#define CP_ASYNC16(sm, gm)                                                      \
    asm volatile("cp.async.cg.shared.global [%0], [%1], 16;" :: "r"(sm), "l"(gm))
#define CP_COMMIT()  asm volatile("cp.async.commit_group;")
#define CP_WAIT1()   asm volatile("cp.async.wait_group 1;")
#define CP_WAIT0()   asm volatile("cp.async.wait_group 0;")

// ---------------- init ----------------
__global__ void init_kernel() {
    int idx = blockIdx.x * blockDim.x + threadIdx.x;
    if (idx < BATCH * NPTS) {
        ((float*)g_pos0)[idx] = 0.0f;
        ((float*)g_pos1)[idx] = 0.0f;
        ((float*)g_mn0)[idx]  = BIG_F;
        ((float*)g_mn1)[idx]  = BIG_F;
    }
}

// ---------------- prep: fp32 -> (hi, lo) bf16 ----------------
__global__ __launch_bounds__(256)
void prep_kernel(const float* __restrict__ d0, const float* __restrict__ d1) {
    size_t t = (size_t)blockIdx.x * 256 + threadIdx.x;
    size_t i = t * 4;                      // 4096 blocks * 256 thr * 4 = 4.19M
    float4 v0 = *(const float4*)(d0 + i);
    float4 v1 = *(const float4*)(d1 + i);
    float a[4] = {v0.x, v0.y, v0.z, v0.w};
    float b[4] = {v1.x, v1.y, v1.z, v1.w};
    __nv_bfloat16 h0[4], l0[4], h1[4], l1[4];
#pragma unroll
    for (int k = 0; k < 4; k++) {
        h0[k] = __float2bfloat16_rn(a[k]);
        l0[k] = __float2bfloat16_rn(a[k] - __bfloat162float(h0[k]));
        h1[k] = __float2bfloat16_rn(b[k]);
        l1[k] = __float2bfloat16_rn(b[k] - __bfloat162float(h1[k]));
    }
    *(__nv_bfloat162*)(g_hi0 + i)     = {h0[0], h0[1]};
    *(__nv_bfloat162*)(g_hi0 + i + 2) = {h0[2], h0[3]};
    *(__nv_bfloat162*)(g_lo0 + i)     = {l0[0], l0[1]};
    *(__nv_bfloat162*)(g_lo0 + i + 2) = {l0[2], l0[3]};
    *(__nv_bfloat162*)(g_hi1 + i)     = {h1[0], h1[1]};
    *(__nv_bfloat162*)(g_hi1 + i + 2) = {h1[2], h1[3]};
    *(__nv_bfloat162*)(g_lo1 + i)     = {l1[0], l1[1]};
    *(__nv_bfloat162*)(g_lo1 + i + 2) = {l1[2], l1[3]};
}

// ---------------------------------------------------------------------------
// pass1: HMMA bf16 GEMM, logical K = 768 (hi*hi + lo*hi + hi*lo),
// tile 128x128, 8 warps (warp tile 64x32), BK=16, 3-stage cp.async pipeline.
// Fused epilogue: dist, match-mask row/col max atomics, neg store.
// ---------------------------------------------------------------------------
#define LDA 136   // 128 + 8 bf16 pad (16B) -> conflict-free ldmatrix.trans
#define NCH 48    // 768 / 16

__global__ __launch_bounds__(256, 2)
void pass1_kernel(const float* __restrict__ mat) {
    const int b  = blockIdx.z;
    const int i0 = blockIdx.y * 128;
    const int j0 = blockIdx.x * 128;

    __shared__ __nv_bfloat16 As[3][16][LDA];
    __shared__ __nv_bfloat16 Bs[3][16][LDA];

    const int tid = threadIdx.x;
    const int w   = tid >> 5;
    const int l   = tid & 31;
    const int m0w = (w & 1) * 64;     // warp tile rows within block
    const int n0w = (w >> 1) * 32;    // warp tile cols within block

    const size_t boff = (size_t)b * DDIM * NPTS;
    const __nv_bfloat16* Aseg[3] = {g_hi0 + boff, g_lo0 + boff, g_hi0 + boff};
    const __nv_bfloat16* Bseg[3] = {g_hi1 + boff, g_hi1 + boff, g_lo1 + boff};

    // loader: each thread moves one 16B chunk of A and one of B per stage
    const int lrow = tid >> 4;          // 0..15
    const int lcol = (tid & 15) * 8;    // bf16 elems

    auto load_stage = [&](int kc) {
        int st  = kc % 3;
        int seg = kc >> 4;
        int kk  = (kc & 15) * 16;
        const __nv_bfloat16* Ag = Aseg[seg] + (size_t)(kk + lrow) * NPTS + i0 + lcol;
        const __nv_bfloat16* Bg = Bseg[seg] + (size_t)(kk + lrow) * NPTS + j0 + lcol;
        uint32_t sa = (uint32_t)__cvta_generic_to_shared(&As[st][lrow][lcol]);
        uint32_t sb = (uint32_t)__cvta_generic_to_shared(&Bs[st][lrow][lcol]);
        CP_ASYNC16(sa, Ag);
        CP_ASYNC16(sb, Bg);
        CP_COMMIT();
    };

    float acc[4][4][4];
#pragma unroll
    for (int mi = 0; mi < 4; mi++)
#pragma unroll
        for (int nj = 0; nj < 4; nj++)
#pragma unroll
            for (int r = 0; r < 4; r++) acc[mi][nj][r] = 0.0f;

    // per-lane ldmatrix address offsets
    const int a_row = ((l >> 4) << 3) + (l & 7);        // k row within 16
    const int a_col = ((l >> 3) & 1) * 8;               // m col offset within 16
    const int b_row = (((l >> 3) & 1) << 3) + (l & 7);  // k row within 16
    const int b_col = (l >> 4) * 8;                     // n col offset within 16

    load_stage(0);
    load_stage(1);

    for (int kc = 0; kc < NCH; kc++) {
        if (kc + 1 < NCH) { CP_WAIT1(); } else { CP_WAIT0(); }
        __syncthreads();
        if (kc + 2 < NCH) load_stage(kc + 2);

        const int st = kc % 3;
        uint32_t a[4][4];
#pragma unroll
        for (int mi = 0; mi < 4; mi++) {
            uint32_t addr = (uint32_t)__cvta_generic_to_shared(
                &As[st][a_row][m0w + mi * 16 + a_col]);
            LDSM_T4(a[mi][0], a[mi][1], a[mi][2], a[mi][3], addr);
        }
        uint32_t bq[2][4];
#pragma unroll
        for (int nb = 0; nb < 2; nb++) {
            uint32_t addr = (uint32_t)__cvta_generic_to_shared(
                &Bs[st][b_row][n0w + nb * 16 + b_col]);
            LDSM_T4(bq[nb][0], bq[nb][1], bq[nb][2], bq[nb][3], addr);
        }
#pragma unroll
        for (int mi = 0; mi < 4; mi++)
#pragma unroll
            for (int nj = 0; nj < 4; nj++)
                MMA16816(acc[mi][nj], a[mi], bq[nj >> 1][(nj & 1) * 2],
                         bq[nj >> 1][(nj & 1) * 2 + 1]);
    }

    // ---- epilogue ----
    const float* Mbase   = mat + (size_t)b * MSTRIDE * MSTRIDE;
    float*       negbase = g_neg + (size_t)b * NPTS * NPTS;

    float cmax[4][2];
#pragma unroll
    for (int nj = 0; nj < 4; nj++) { cmax[nj][0] = 0.0f; cmax[nj][1] = 0.0f; }

#pragma unroll
    for (int mi = 0; mi < 4; mi++) {
#pragma unroll
        for (int h = 0; h < 2; h++) {
            const int r = i0 + m0w + mi * 16 + (l >> 2) + h * 8;
            const float* Mr = Mbase + (size_t)r * MSTRIDE;
            float* Nr = negbase + (size_t)r * NPTS;
            float rm = 0.0f;
#pragma unroll
            for (int nj = 0; nj < 4; nj++) {
                const int cb = j0 + n0w + nj * 8 + (l & 3) * 2;
                float v0 = acc[mi][nj][h * 2 + 0];
                float v1 = acc[mi][nj][h * 2 + 1];
                float dA = fmaf(-2.0f, v0, 2.0f);
                float dB = fmaf(-2.0f, v1, 2.0f);
                float ovA = __ldg(Mr + cb);
                float ovB = __ldg(Mr + cb + 1);
                if (ovA > 0.3f) { rm = fmaxf(rm, dA); cmax[nj][0] = fmaxf(cmax[nj][0], dA); }
                if (ovB > 0.3f) { rm = fmaxf(rm, dB); cmax[nj][1] = fmaxf(cmax[nj][1], dB); }
                float nA = (ovA <= 0.0f) ? dA : MAXDIST_F;
                float nB = (ovB <= 0.0f) ? dB : MAXDIST_F;
                *(float2*)(Nr + cb) = make_float2(nA, nB);
            }
            // row max over the 4 lanes sharing this row (bits 0,1 of lane)
            rm = fmaxf(rm, __shfl_xor_sync(0xffffffffu, rm, 1));
            rm = fmaxf(rm, __shfl_xor_sync(0xffffffffu, rm, 2));
            if ((l & 3) == 0)
                atomicMax((int*)&g_pos0[b][r], __float_as_int(rm));
        }
    }
    // col max: reduce over lanes sharing (l&3) (bits 2,3,4)
#pragma unroll
    for (int nj = 0; nj < 4; nj++) {
#pragma unroll
        for (int p = 0; p < 2; p++) {
            float cm = cmax[nj][p];
            cm = fmaxf(cm, __shfl_xor_sync(0xffffffffu, cm, 4));
            cm = fmaxf(cm, __shfl_xor_sync(0xffffffffu, cm, 8));
            cm = fmaxf(cm, __shfl_xor_sync(0xffffffffu, cm, 16));
            if (l < 4)
                atomicMax((int*)&g_pos1[b][j0 + n0w + nj * 8 + (l & 3) * 2 + p],
                          __float_as_int(cm));
        }
    }
}

// ---------------------------------------------------------------------------
// pass2: masked min using finalized pos0/pos1 against stored neg
// ---------------------------------------------------------------------------
__global__ __launch_bounds__(256)
void pass2_kernel() {
    const int b  = blockIdx.z;
    const int i0 = blockIdx.y * 128;
    const int j0 = blockIdx.x * 128;

    const int tid = threadIdx.x;
    const int tx = tid & 15;
    const int ty = tid >> 4;

    __shared__ float cbuf[16 * 128];

    const float* negbase = g_neg + (size_t)b * NPTS * NPTS;

    float p1[8];
#pragma unroll
    for (int c = 0; c < 8; c++) p1[c] = g_pos1[b][j0 + tx * 8 + c];

    float rmin[8], cmin[8];
#pragma unroll
    for (int r = 0; r < 8; r++) { rmin[r] = BIG_F; cmin[r] = BIG_F; }

#pragma unroll
    for (int r = 0; r < 8; r++) {
        const int i = i0 + ty * 8 + r;
        const float p0 = g_pos0[b][i];
        const float p0hi = p0 + MARGIN_F;
        const float* Nr = negbase + (size_t)i * NPTS + j0 + tx * 8;
        float4 v0 = *(const float4*)Nr;
        float4 v1 = *(const float4*)(Nr + 4);
        float nv[8] = {v0.x, v0.y, v0.z, v0.w, v1.x, v1.y, v1.z, v1.w};
#pragma unroll
        for (int c = 0; c < 8; c++) {
            float v = nv[c];
            if (v > p0 && v < p0hi)                 rmin[r] = fminf(rmin[r], v);
            if (v > p1[c] && v < p1[c] + MARGIN_F)  cmin[c] = fminf(cmin[c], v);
        }
    }

#pragma unroll
    for (int r = 0; r < 8; r++) {
#pragma unroll
        for (int s = 8; s > 0; s >>= 1)
            rmin[r] = fminf(rmin[r], __shfl_xor_sync(0xffffffffu, rmin[r], s));
    }
    if (tx == 0) {
#pragma unroll
        for (int r = 0; r < 8; r++)
            atomicMin((int*)&g_mn0[b][i0 + ty * 8 + r], __float_as_int(rmin[r]));
    }

#pragma unroll
    for (int c = 0; c < 8; c++)
        cbuf[ty * 128 + tx * 8 + c] = cmin[c];
    __syncthreads();
    if (tid < 128) {
        float m = BIG_F;
#pragma unroll
        for (int rr = 0; rr < 16; rr++)
            m = fminf(m, cbuf[rr * 128 + tid]);
        atomicMin((int*)&g_mn1[b][j0 + tid], __float_as_int(m));
    }
}

// ---------------------------------------------------------------------------
// final reduction: 64-block partial + tiny finalize
// ---------------------------------------------------------------------------
__global__ __launch_bounds__(256)
void partial_kernel() {
    const int tid = threadIdx.x;
    float sum = 0.0f, cnt = 0.0f, hp = -BIG_F, hn = BIG_F;

    for (int idx = blockIdx.x * 256 + tid; idx < 2 * BATCH * NPTS; idx += 64 * 256) {
        int b = idx >> 13;
        int r = idx & 8191;
        float pos, mn;
        if (r < NPTS) { pos = g_pos0[b][r]; mn = g_mn0[b][r]; }
        else          { pos = g_pos1[b][r - NPTS]; mn = g_mn1[b][r - NPTS]; }
        bool valid = (pos > 0.0f) && (mn < BIG_F);
        if (valid) {
            sum += fmaxf(pos - mn + 1.0f, 0.0f);
            cnt += 1.0f;
            hp = fmaxf(hp, pos);
            hn = fminf(hn, mn);
        }
    }

    __shared__ float s_sum[8], s_cnt[8], s_hp[8], s_hn[8];
#pragma unroll
    for (int s = 16; s > 0; s >>= 1) {
        sum += __shfl_xor_sync(0xffffffffu, sum, s);
        cnt += __shfl_xor_sync(0xffffffffu, cnt, s);
        hp = fmaxf(hp, __shfl_xor_sync(0xffffffffu, hp, s));
        hn = fminf(hn, __shfl_xor_sync(0xffffffffu, hn, s));
    }
    if ((tid & 31) == 0) {
        s_sum[tid >> 5] = sum; s_cnt[tid >> 5] = cnt;
        s_hp[tid >> 5] = hp;   s_hn[tid >> 5] = hn;
    }
    __syncthreads();
    if (tid == 0) {
        sum = 0.0f; cnt = 0.0f; hp = -BIG_F; hn = BIG_F;
#pragma unroll
        for (int i = 0; i < 8; i++) {
            sum += s_sum[i]; cnt += s_cnt[i];
            hp = fmaxf(hp, s_hp[i]); hn = fminf(hn, s_hn[i]);
        }
        g_psum[blockIdx.x] = sum; g_pcnt[blockIdx.x] = cnt;
        g_php[blockIdx.x] = hp;   g_phn[blockIdx.x] = hn;
    }
}

__global__ void finalize_kernel(float* __restrict__ out) {
    const int tid = threadIdx.x;   // 32 threads
    float sum = g_psum[tid] + g_psum[tid + 32];
    float cnt = g_pcnt[tid] + g_pcnt[tid + 32];
    float hp  = fmaxf(g_php[tid], g_php[tid + 32]);
    float hn  = fminf(g_phn[tid], g_phn[tid + 32]);
#pragma unroll
    for (int s = 16; s > 0; s >>= 1) {
        sum += __shfl_xor_sync(0xffffffffu, sum, s);
        cnt += __shfl_xor_sync(0xffffffffu, cnt, s);
        hp = fmaxf(hp, __shfl_xor_sync(0xffffffffu, hp, s));
        hn = fminf(hn, __shfl_xor_sync(0xffffffffu, hn, s));
    }
    if (tid == 0) {
        out[0] = sum / fmaxf(cnt, 1.0f);
        out[1] = hp;
        out[2] = hn;
    }
}

// ---------------------------------------------------------------------------
extern "C" void kernel_launch(void* const* d_in, const int* in_sizes, int n_in,
                              void* d_out, int out_size) {
    const float* desc0 = (const float*)d_in[0];
    const float* desc1 = (const float*)d_in[1];
    const float* mat   = (const float*)d_in[2];
    float* out = (float*)d_out;

    init_kernel<<<16, 1024>>>();
    prep_kernel<<<4096, 256>>>(desc0, desc1);
    dim3 grid(NPTS / 128, NPTS / 128, BATCH);
    pass1_kernel<<<grid, 256>>>(mat);
    pass2_kernel<<<grid, 256>>>();
    partial_kernel<<<64, 256>>>();
    finalize_kernel<<<1, 32>>>(out);
}